// round 1
// baseline (speedup 1.0000x reference)
#include <cuda_runtime.h>

#define B_ 32
#define N_ 65536
#define CHUNKS 32          // blocks per batch in pass1
#define TPB 256

// Deterministic per-block partials: [b][block][27]  (21 sym H_eff + 6 g_eff)
__device__ float g_part[B_][CHUNKS][27];
// Per-point scratch for back-substitution: [b][n][8] = H_pd[6], inv_H_dd, g_d
__device__ float g_scratch[(size_t)B_ * N_ * 8];

// ---------------------------------------------------------------------------
// Pass 1: single sweep over inputs. Accumulates the Schur-complement-reduced
// 6x6 system per batch and stores per-point scratch for pass 2.
// ---------------------------------------------------------------------------
__global__ __launch_bounds__(TPB) void pass1_kernel(
    const float* __restrict__ r, const float* __restrict__ w,
    const float* __restrict__ Jp, const float* __restrict__ Jd,
    const float* __restrict__ lmbda)
{
    const int b = blockIdx.y;
    const float lam = __ldg(lmbda);

    float acc[27];
#pragma unroll
    for (int v = 0; v < 27; v++) acc[v] = 0.f;

    const int   gtid   = blockIdx.x * TPB + threadIdx.x;
    const int   stride = CHUNKS * TPB;
    const size_t base2  = (size_t)b * N_ * 2;
    const size_t base12 = (size_t)b * N_ * 12;

    for (int n = gtid; n < N_; n += stride) {
        float2 rv = *(const float2*)(r  + base2 + 2 * (size_t)n);
        float2 wv = *(const float2*)(w  + base2 + 2 * (size_t)n);
        float2 dv = *(const float2*)(Jd + base2 + 2 * (size_t)n);
        const float4* jp4 = (const float4*)(Jp + base12 + 12 * (size_t)n);
        float4 a0 = jp4[0], a1 = jp4[1], a2 = jp4[2];
        float p0[6] = {a0.x, a0.y, a0.z, a0.w, a1.x, a1.y};
        float p1[6] = {a1.z, a1.w, a2.x, a2.y, a2.z, a2.w};

        float wd0 = wv.x * dv.x, wd1 = wv.y * dv.y;   // w*Jd per k
        float wr0 = wv.x * rv.x, wr1 = wv.y * rv.y;   // w*r  per k

        float Hdd = dv.x * wd0 + dv.y * wd1 + lam;    // sum_k Jd^2 w + lambda
        float gd  = rv.x * wd0 + rv.y * wd1;          // sum_k Jd w r
        float inv = 1.f / (Hdd + 1e-8f);

        float hpd[6], ti[6];
#pragma unroll
        for (int i = 0; i < 6; i++) {
            hpd[i] = p0[i] * wd0 + p1[i] * wd1;       // H_pd_i
            ti[i]  = hpd[i] * inv;
        }

        // scratch for pass 2
        float4* sc = (float4*)(g_scratch + ((size_t)b * N_ + n) * 8);
        sc[0] = make_float4(hpd[0], hpd[1], hpd[2], hpd[3]);
        sc[1] = make_float4(hpd[4], hpd[5], inv, gd);

        float q0[6], q1[6];
#pragma unroll
        for (int i = 0; i < 6; i++) { q0[i] = p0[i] * wv.x; q1[i] = p1[i] * wv.y; }

        // H_eff (upper triangle): sum_k Jp_i w Jp_j  -  H_pd_i inv H_pd_j
        int c = 0;
#pragma unroll
        for (int i = 0; i < 6; i++)
#pragma unroll
            for (int j = i; j < 6; j++, c++)
                acc[c] += q0[i] * p0[j] + q1[i] * p1[j] - ti[i] * hpd[j];

        // g_eff: sum_k Jp_i w r  -  H_pd_i inv g_d
        float s = inv * gd;
#pragma unroll
        for (int i = 0; i < 6; i++)
            acc[21 + i] += p0[i] * wr0 + p1[i] * wr1 - hpd[i] * s;
    }

    // warp reduce all 27
#pragma unroll
    for (int v = 0; v < 27; v++)
#pragma unroll
        for (int off = 16; off; off >>= 1)
            acc[v] += __shfl_down_sync(0xffffffffu, acc[v], off);

    __shared__ float swarp[TPB / 32][27];
    const int wid = threadIdx.x >> 5, lid = threadIdx.x & 31;
    if (lid == 0) {
#pragma unroll
        for (int v = 0; v < 27; v++) swarp[wid][v] = acc[v];
    }
    __syncthreads();
    if (threadIdx.x < 27) {
        float s = 0.f;
#pragma unroll
        for (int wv = 0; wv < TPB / 32; wv++) s += swarp[wv][threadIdx.x];
        g_part[b][blockIdx.x][threadIdx.x] = s;  // deterministic, no atomics
    }
}

// ---------------------------------------------------------------------------
// Solve: 32 threads, one 6x6 system each. Sum block-partials, add (lam+eps)*I,
// Gaussian elimination with partial pivoting in double.
// ---------------------------------------------------------------------------
__global__ void solve_kernel(const float* __restrict__ lmbda,
                             float* __restrict__ out_pose)
{
    const int b = threadIdx.x;
    if (b >= B_) return;
    const float lam = __ldg(lmbda);

    float sum[27];
#pragma unroll
    for (int v = 0; v < 27; v++) {
        float s = 0.f;
        for (int c = 0; c < CHUNKS; c++) s += g_part[b][c][v];
        sum[v] = s;
    }

    double A[6][7];
    int c = 0;
    for (int i = 0; i < 6; i++)
        for (int j = i; j < 6; j++, c++) {
            A[i][j] = sum[c];
            A[j][i] = sum[c];
        }
    for (int i = 0; i < 6; i++) {
        A[i][i] += (double)lam + 1e-4;   // lambda*I (H_pp) + eps*I (H_eff)
        A[i][6]  = sum[21 + i];          // g_eff
    }

    // Gaussian elimination with partial pivoting
    for (int col = 0; col < 6; col++) {
        int p = col;
        double mx = fabs(A[col][col]);
        for (int rr = col + 1; rr < 6; rr++) {
            double v = fabs(A[rr][col]);
            if (v > mx) { mx = v; p = rr; }
        }
        if (p != col)
            for (int j = col; j < 7; j++) {
                double t = A[col][j]; A[col][j] = A[p][j]; A[p][j] = t;
            }
        double pinv = 1.0 / A[col][col];
        for (int rr = col + 1; rr < 6; rr++) {
            double f = A[rr][col] * pinv;
            for (int j = col; j < 7; j++) A[rr][j] -= f * A[col][j];
        }
    }
    double x[6];
    for (int i = 5; i >= 0; i--) {
        double s = A[i][6];
        for (int j = i + 1; j < 6; j++) s -= A[i][j] * x[j];
        x[i] = s / A[i][i];
    }
    for (int i = 0; i < 6; i++) out_pose[b * 6 + i] = (float)x[i];
}

// ---------------------------------------------------------------------------
// Pass 2: delta_depth = inv_H_dd * (g_d - H_pd . delta_pose)
// ---------------------------------------------------------------------------
__global__ __launch_bounds__(256) void pass2_kernel(
    const float* __restrict__ pose, float* __restrict__ depth)
{
    const int b = blockIdx.y;
    __shared__ float dp[6];
    if (threadIdx.x < 6) dp[threadIdx.x] = pose[b * 6 + threadIdx.x];
    __syncthreads();

    const int n = blockIdx.x * blockDim.x + threadIdx.x;
    if (n < N_) {
        const float4* sc = (const float4*)(g_scratch + ((size_t)b * N_ + n) * 8);
        float4 s0 = sc[0], s1 = sc[1];
        float v = s0.x * dp[0] + s0.y * dp[1] + s0.z * dp[2] +
                  s0.w * dp[3] + s1.x * dp[4] + s1.y * dp[5];
        depth[(size_t)b * N_ + n] = s1.z * (s1.w - v);
    }
}

// ---------------------------------------------------------------------------
extern "C" void kernel_launch(void* const* d_in, const int* in_sizes, int n_in,
                              void* d_out, int out_size)
{
    const float* r  = (const float*)d_in[0];
    const float* w  = (const float*)d_in[1];
    const float* Jp = (const float*)d_in[2];
    const float* Jd = (const float*)d_in[3];
    const float* lm = (const float*)d_in[4];

    float* out   = (float*)d_out;
    float* pose  = out;            // [B,6]   (reference returns delta_pose first)
    float* depth = out + B_ * 6;   // [B,N]

    dim3 g1(CHUNKS, B_);
    pass1_kernel<<<g1, TPB>>>(r, w, Jp, Jd, lm);
    solve_kernel<<<1, 32>>>(lm, pose);
    dim3 g2(N_ / 256, B_);
    pass2_kernel<<<g2, 256>>>(pose, depth);
}